// round 13
// baseline (speedup 1.0000x reference)
#include <cuda_runtime.h>
#include <cuda_fp16.h>
#include <cstdint>
#include <cstddef>

// ---------------------------------------------------------------------------
// Problem constants
// ---------------------------------------------------------------------------
#define B_  2
#define S_  2048
#define D_  2048
#define H_  16
#define HD_ 128
#define M_  (B_*S_)            // 4096 rows
#define K_  2048               // inner dim of BOTH gemms (compile-time)
#define SCALE_ 0.08838834764831845f

// ---------------------------------------------------------------------------
// Scratch (__device__ globals; no allocation allowed)
// ---------------------------------------------------------------------------
__device__ __half g_xh[(size_t)M_ * D_];                // x single fp16
__device__ __half g_w1h[(size_t)3 * D_ * D_];           // Wqkv^T [6144,2048] fp16
__device__ __half g_w2h[(size_t)D_ * D_];               // Wo^T [2048,2048] fp16
// q (pre-scaled), k, v single fp16.  [B,H,S,HD]
__device__ __half g_qh[(size_t)M_ * D_];
__device__ __half g_kh[(size_t)M_ * D_];
__device__ __half g_vh[(size_t)M_ * D_];
// attention output [B,S,D] single fp16 (feeds proj)
__device__ __half g_ah[(size_t)M_ * D_];

// ---------------------------------------------------------------------------
// Portable PTX helpers (virtual arch compute_103: no tcgen05)
// ---------------------------------------------------------------------------
__device__ __forceinline__ uint32_t smem_u32(const void* p) {
    uint32_t a;
    asm("{ .reg .u64 t; cvta.to.shared.u64 t, %1; cvt.u32.u64 %0, t; }"
        : "=r"(a) : "l"(p));
    return a;
}

#define CP16(dst_u32, src_ptr) \
    asm volatile("cp.async.cg.shared.global [%0], [%1], 16;" \
                 :: "r"(dst_u32), "l"(src_ptr) : "memory")
#define CP_COMMIT() asm volatile("cp.async.commit_group;" ::: "memory")
#define CP_WAIT(n)  asm volatile("cp.async.wait_group %0;" :: "n"(n) : "memory")

#define LDSM_X4(r0, r1, r2, r3, addr) \
    asm volatile("ldmatrix.sync.aligned.m8n8.x4.shared.b16 {%0,%1,%2,%3}, [%4];" \
                 : "=r"(r0), "=r"(r1), "=r"(r2), "=r"(r3) : "r"(addr))
#define LDSM_X4T(r0, r1, r2, r3, addr) \
    asm volatile("ldmatrix.sync.aligned.m8n8.x4.trans.shared.b16 {%0,%1,%2,%3}, [%4];" \
                 : "=r"(r0), "=r"(r1), "=r"(r2), "=r"(r3) : "r"(addr))

__device__ __forceinline__ void mma16816h(float* d, const uint32_t* a,
                                          const uint32_t* b) {
    asm volatile(
        "mma.sync.aligned.m16n8k16.row.col.f32.f16.f16.f32 "
        "{%0,%1,%2,%3}, {%4,%5,%6,%7}, {%8,%9}, {%0,%1,%2,%3};"
        : "+f"(d[0]), "+f"(d[1]), "+f"(d[2]), "+f"(d[3])
        : "r"(a[0]), "r"(a[1]), "r"(a[2]), "r"(a[3]), "r"(b[0]), "r"(b[1]));
}

// pack two floats -> fp16x2 hi + fp16x2 lo(residual)
__device__ __forceinline__ void packhl_h(float x, float y, uint32_t& hp, uint32_t& lp) {
    __half2 hv = __floats2half2_rn(x, y);
    float rx = x - __half2float(__low2half(hv));
    float ry = y - __half2float(__high2half(hv));
    __half2 lv = __floats2half2_rn(rx, ry);
    hp = *reinterpret_cast<uint32_t*>(&hv);
    lp = *reinterpret_cast<uint32_t*>(&lv);
}

// ---------------------------------------------------------------------------
// convert / transpose pre-passes
// ---------------------------------------------------------------------------
__global__ void convert_f32_h(const float* __restrict__ in,
                              __half* __restrict__ out, int n4) {
    int i = blockIdx.x * blockDim.x + threadIdx.x;
    if (i >= n4) return;
    float4 v = *(const float4*)(in + (size_t)i * 4);
    __half2 a = __floats2half2_rn(v.x, v.y);
    __half2 b = __floats2half2_rn(v.z, v.w);
    __half2* op = (__half2*)(out + (size_t)i * 4);
    op[0] = a; op[1] = b;
}

__global__ void transpose_h(const float* __restrict__ W,
                            __half* __restrict__ Th, int K, int N) {
    __shared__ float t[32][33];
    int n0 = blockIdx.x * 32, k0 = blockIdx.y * 32;
    int tx = threadIdx.x, ty = threadIdx.y;      // (32,8)
    #pragma unroll
    for (int j = 0; j < 32; j += 8)
        t[ty + j][tx] = W[(size_t)(k0 + ty + j) * N + n0 + tx];
    __syncthreads();
    #pragma unroll
    for (int j = 0; j < 32; j += 8)
        Th[(size_t)(n0 + ty + j) * K + k0 + tx] = __float2half(t[tx][ty + j]);
}

// ---------------------------------------------------------------------------
// shared swizzle: 64B rows, chunk ^= (row>>1)&3
// ---------------------------------------------------------------------------
#define GBK 32
#define GSWZ(r, c) ((uint32_t)(r) * 64u + ((((uint32_t)(c) ^ (((uint32_t)(r) >> 1) & 3u))) << 4))

// ---------------------------------------------------------------------------
// QKV GEMM (fp16x1):  BM=128, BN=192, BK=32, 8 warps (2x4), warp 64x48,
// 4-stage cp.async.  Epilogue: bias (+scale for q); single fp16 q/k/v.
// ---------------------------------------------------------------------------
#define QOFF_A 0
#define QOFF_B 8192                   // A: 128 rows * 64B = 8192
#define QSTAGEB 20480                 // + B: 192 rows * 64B = 12288
#define QNSTAGE 4
#define QKV_DYN_SMEM (QNSTAGE * QSTAGEB)   // 81920

__global__ __launch_bounds__(256, 1) void gemm_qkv(
    const __half* __restrict__ Am, const __half* __restrict__ Bm,
    const float* __restrict__ bias,
    __half* __restrict__ qh, __half* __restrict__ kh, __half* __restrict__ vh)
{
    extern __shared__ __align__(128) char sm[];
    const uint32_t sbase = smem_u32(sm);

    const int tid = threadIdx.x;
    const int wid = tid >> 5;
    const int lane = tid & 31;
    const int m0 = blockIdx.y * 128;
    const int n0 = blockIdx.x * 192;
    const int wm = (wid >> 2) * 64;      // 0 / 64
    const int wn = (wid & 3) * 48;       // 0/48/96/144

    const int tr = tid >> 2;             // 0..63
    const int pc = tid & 3;              // chunk 0..3
    const __half* pA = Am + (m0 + tr) * K_ + pc * 8;
    const __half* pB = Bm + (n0 + tr) * K_ + pc * 8;
    const uint32_t dT0 = GSWZ(tr, pc);
    const uint32_t dT1 = GSWZ(tr + 64, pc);
    const uint32_t dT2 = GSWZ(tr + 128, pc);

    auto produce = [&](int stg, int kblk) {
        uint32_t s = sbase + stg * QSTAGEB;
        CP16(s + QOFF_A + dT0, pA + kblk);
        CP16(s + QOFF_A + dT1, pA + 64 * K_ + kblk);
        CP16(s + QOFF_B + dT0, pB + kblk);
        CP16(s + QOFF_B + dT1, pB + 64 * K_ + kblk);
        CP16(s + QOFF_B + dT2, pB + 128 * K_ + kblk);
    };

    float acc[4][6][4];
    #pragma unroll
    for (int i = 0; i < 4; i++)
        #pragma unroll
        for (int j = 0; j < 6; j++)
            #pragma unroll
            for (int r = 0; r < 4; r++) acc[i][j][r] = 0.f;

    uint32_t aoff[4], boff[3];
    #pragma unroll
    for (int ti = 0; ti < 4; ti++)
        aoff[ti] = GSWZ(wm + ti * 16 + (lane & 15), (lane >> 4));
    #pragma unroll
    for (int pj = 0; pj < 3; pj++)
        boff[pj] = GSWZ(wn + pj * 16 + (lane & 7) + ((lane >> 4) & 1) * 8,
                        ((lane >> 3) & 1));

    auto compute = [&](int stg) {
        uint32_t s = sbase + stg * QSTAGEB;
        #pragma unroll
        for (int ks = 0; ks < 2; ks++) {
            const uint32_t kx = ks ? 0x20u : 0u;
            uint32_t ah[4][4];
            #pragma unroll
            for (int ti = 0; ti < 4; ti++) {
                uint32_t ad = s + QOFF_A + (aoff[ti] ^ kx);
                LDSM_X4(ah[ti][0], ah[ti][1], ah[ti][2], ah[ti][3], ad);
            }
            #pragma unroll
            for (int pj = 0; pj < 3; pj++) {
                uint32_t bd = s + QOFF_B + (boff[pj] ^ kx);
                uint32_t h0, h1, h2, h3;
                LDSM_X4(h0, h1, h2, h3, bd);
                uint32_t bh0[2] = {h0, h1}, bh1[2] = {h2, h3};
                #pragma unroll
                for (int ti = 0; ti < 4; ti++) {
                    mma16816h(acc[ti][2 * pj],     ah[ti], bh0);
                    mma16816h(acc[ti][2 * pj + 1], ah[ti], bh1);
                }
            }
        }
    };

    const int NK = K_ / GBK;             // 64
    produce(0, 0); CP_COMMIT();
    produce(1, GBK); CP_COMMIT();
    produce(2, 2 * GBK); CP_COMMIT();

    for (int it = 0; it < NK; ++it) {
        CP_WAIT(2);
        __syncthreads();
        compute(it & (QNSTAGE - 1));
        if (it + 3 < NK) produce((it + 3) & (QNSTAGE - 1), (it + 3) * GBK);
        CP_COMMIT();
    }

    // ---- epilogue: single fp16 q (scaled) / k / v ----
    const int er = lane >> 2;
    const int ec = (lane & 3) * 2;
    #pragma unroll
    for (int tj = 0; tj < 6; tj++) {
        int col = n0 + wn + tj * 8 + ec;
        int hh = col / 384, rem = col % 384;
        int which = rem >> 7, hd = rem & 127;
        __half* dst = which == 0 ? qh : (which == 1 ? kh : vh);
        float sc = which == 0 ? SCALE_ : 1.0f;
        float bx = bias[col], by = bias[col + 1];
        #pragma unroll
        for (int ti = 0; ti < 4; ti++) {
            #pragma unroll
            for (int rr = 0; rr < 2; rr++) {
                int row = m0 + wm + ti * 16 + er + rr * 8;
                int bb = row >> 11, ss = row & 2047;
                size_t off = (((size_t)(bb * H_ + hh)) * S_ + ss) * HD_ + hd;
                float vx = (acc[ti][tj][rr * 2] + bx) * sc;
                float vy = (acc[ti][tj][rr * 2 + 1] + by) * sc;
                *(__half2*)(dst + off) = __floats2half2_rn(vx, vy);
            }
        }
    }
}

// ---------------------------------------------------------------------------
// Proj GEMM (fp16x1):  C = A @ Bt^T + bias.  A single fp16, B single fp16.
// BM=128, BN=256, BK=32, 8 warps (2x4), warp 64x64, 4-stage cp.async.
// ---------------------------------------------------------------------------
#define POFF_A 0
#define POFF_B 8192                   // A: 128 rows * 64B
#define PSTAGEB 24576                 // + B: 256 rows * 64B = 16384
#define PNSTAGE 4
#define PROJ_DYN_SMEM (PNSTAGE * PSTAGEB)   // 98304

__global__ __launch_bounds__(256, 1) void gemm_proj(
    const __half* __restrict__ Am, const __half* __restrict__ Bm,
    const float* __restrict__ bias, float* __restrict__ C)
{
    extern __shared__ __align__(128) char sm[];
    const uint32_t sbase = smem_u32(sm);

    const int tid = threadIdx.x;
    const int wid = tid >> 5;
    const int lane = tid & 31;
    const int m0 = blockIdx.y * 128;
    const int n0 = blockIdx.x * 256;
    const int wm = (wid >> 2) * 64;
    const int wn = (wid & 3) * 64;

    const int tr = tid >> 2;
    const int pc = tid & 3;
    const __half* pA = Am + (m0 + tr) * K_ + pc * 8;
    const __half* pB = Bm + (n0 + tr) * K_ + pc * 8;
    const uint32_t dT0 = GSWZ(tr, pc);
    const uint32_t dT1 = GSWZ(tr + 64, pc);
    const uint32_t dT2 = GSWZ(tr + 128, pc);
    const uint32_t dT3 = GSWZ(tr + 192, pc);

    auto produce = [&](int stg, int kblk) {
        uint32_t s = sbase + stg * PSTAGEB;
        CP16(s + POFF_A + dT0, pA + kblk);
        CP16(s + POFF_A + dT1, pA + 64 * K_ + kblk);
        CP16(s + POFF_B + dT0, pB + kblk);
        CP16(s + POFF_B + dT1, pB + 64 * K_ + kblk);
        CP16(s + POFF_B + dT2, pB + 128 * K_ + kblk);
        CP16(s + POFF_B + dT3, pB + 192 * K_ + kblk);
    };

    float acc[4][8][4];
    #pragma unroll
    for (int i = 0; i < 4; i++)
        #pragma unroll
        for (int j = 0; j < 8; j++)
            #pragma unroll
            for (int r = 0; r < 4; r++) acc[i][j][r] = 0.f;

    uint32_t aoff[4], boff[4];
    #pragma unroll
    for (int ti = 0; ti < 4; ti++)
        aoff[ti] = GSWZ(wm + ti * 16 + (lane & 15), (lane >> 4));
    #pragma unroll
    for (int pj = 0; pj < 4; pj++)
        boff[pj] = GSWZ(wn + pj * 16 + (lane & 7) + ((lane >> 4) & 1) * 8,
                        ((lane >> 3) & 1));

    auto compute = [&](int stg) {
        uint32_t s = sbase + stg * PSTAGEB;
        #pragma unroll
        for (int ks = 0; ks < 2; ks++) {
            const uint32_t kx = ks ? 0x20u : 0u;
            uint32_t ah[4][4];
            #pragma unroll
            for (int ti = 0; ti < 4; ti++) {
                uint32_t ad = s + POFF_A + (aoff[ti] ^ kx);
                LDSM_X4(ah[ti][0], ah[ti][1], ah[ti][2], ah[ti][3], ad);
            }
            #pragma unroll
            for (int pj = 0; pj < 4; pj++) {
                uint32_t bd = s + POFF_B + (boff[pj] ^ kx);
                uint32_t h0, h1, h2, h3;
                LDSM_X4(h0, h1, h2, h3, bd);
                uint32_t bh0[2] = {h0, h1}, bh1[2] = {h2, h3};
                #pragma unroll
                for (int ti = 0; ti < 4; ti++) {
                    mma16816h(acc[ti][2 * pj],     ah[ti], bh0);
                    mma16816h(acc[ti][2 * pj + 1], ah[ti], bh1);
                }
            }
        }
    };

    const int NK = K_ / GBK;
    produce(0, 0); CP_COMMIT();
    produce(1, GBK); CP_COMMIT();
    produce(2, 2 * GBK); CP_COMMIT();

    for (int it = 0; it < NK; ++it) {
        CP_WAIT(2);
        __syncthreads();
        compute(it & (PNSTAGE - 1));
        if (it + 3 < NK) produce((it + 3) & (PNSTAGE - 1), (it + 3) * GBK);
        CP_COMMIT();
    }

    const int er = lane >> 2;
    const int ec = (lane & 3) * 2;
    #pragma unroll
    for (int tj = 0; tj < 8; tj++) {
        int col = n0 + wn + tj * 8 + ec;
        float bx = bias[col], by = bias[col + 1];
        #pragma unroll
        for (int ti = 0; ti < 4; ti++) {
            int row = m0 + wm + ti * 16 + er;
            float2 v0 = { acc[ti][tj][0] + bx, acc[ti][tj][1] + by };
            float2 v1 = { acc[ti][tj][2] + bx, acc[ti][tj][3] + by };
            *(float2*)(C + (size_t)row * D_ + col) = v0;
            *(float2*)(C + (size_t)(row + 8) * D_ + col) = v1;
        }
    }
}

// ---------------------------------------------------------------------------
// HMMA causal flash attention: BQ=256 (8 warps x 32 q-rows, ti=2),
// Q/K single fp16 (1 term), P fp16 hi/lo x V single fp16 (2 terms).
// K fragment shared across ti in phase 1; V fragment shared across ti+hi/lo
// in phase 2 (HMMA:LDSM = 4.8, tensor-bound).  BKV=64, HD=128, double buffer.
// ---------------------------------------------------------------------------
#define FBQ 256
#define FROWB 272                      // 128 fp16 + 8 pad = 136 elems
#define FQBYTES (FBQ * FROWB)          // Q tile: 69632
#define FKBYTES (64 * FROWB)           // per K/V array: 17408
#define FSTGB (2 * FKBYTES)            // k, v: 34816
#define FLASH_DYN_SMEM (FQBYTES + 2 * FSTGB)   // 139264 B

__global__ __launch_bounds__(256, 1) void flash_mma(
    const __half* __restrict__ qh_,
    const __half* __restrict__ kh_, const __half* __restrict__ vh_,
    __half* __restrict__ oh_)
{
    extern __shared__ __align__(128) char fsm[];
    const uint32_t sb = smem_u32(fsm);
    const int tid = threadIdx.x, wq = tid >> 5, lane = tid & 31;
    const int bi = (int)gridDim.x - 1 - (int)blockIdx.x;   // big blocks first
    const int hh = blockIdx.y, b = blockIdx.z;
    const int q0 = bi * FBQ;
    const size_t bh = ((size_t)b * H_ + hh) * S_;
    const uint32_t QH = sb;
    const uint32_t KV0 = sb + FQBYTES;

    // Q tile load: 256 rows x 128 -> 16 CP16/thread
    #pragma unroll
    for (int i = 0; i < 16; i++) {
        int id = tid + i * 256;
        int r = id >> 4, c = id & 15;
        size_t src = (bh + q0 + r) * HD_ + c * 8;
        CP16(QH + r * FROWB + c * 16, qh_ + src);
    }
    auto produce = [&](int stg, int kt) {
        uint32_t s = KV0 + stg * FSTGB;
        int k0 = kt * 64;
        #pragma unroll
        for (int i = 0; i < 4; i++) {
            int id = tid + i * 256;
            int r = id >> 4, c = id & 15;
            size_t src = (bh + k0 + r) * HD_ + c * 8;
            uint32_t d = r * FROWB + c * 16;
            CP16(s + d, kh_ + src);
            CP16(s + FKBYTES + d, vh_ + src);
        }
    };

    float o[2][16][4];
    #pragma unroll
    for (int t = 0; t < 2; t++)
        #pragma unroll
        for (int j = 0; j < 16; j++)
            #pragma unroll
            for (int r = 0; r < 4; r++) o[t][j][r] = 0.f;
    float m[2][2] = {{-1e30f, -1e30f}, {-1e30f, -1e30f}};
    float l[2][2] = {{0.f, 0.f}, {0.f, 0.f}};

    const int er = lane >> 2, ec2 = (lane & 3) * 2;
    const uint32_t a_row0 = wq * 32 + (lane & 15);       // ti=0; ti=1: +16
    const uint32_t a_kb  = (lane >> 4) * 16;
    const uint32_t b_row = (lane & 7) + ((lane >> 4) & 1) * 8;
    const uint32_t b_kb  = ((lane >> 3) & 1) * 16;
    const uint32_t v_row = (lane & 7) + ((lane >> 3) & 1) * 8;
    const uint32_t v_cb  = ((lane >> 4) & 1) * 16;

    const int nkt = 4 * bi + 4;
    produce(0, 0);
    CP_COMMIT();

    for (int kt = 0; kt < nkt; kt++) {
        if (kt + 1 < nkt) { produce((kt + 1) & 1, kt + 1); CP_COMMIT(); CP_WAIT(1); }
        else CP_WAIT(0);
        __syncthreads();
        const uint32_t kb = KV0 + (kt & 1) * FSTGB;

        // ---- phase 1: S = Q K^T for both ti; K frag shared ----
        float s[2][8][4];
        #pragma unroll
        for (int t = 0; t < 2; t++)
            #pragma unroll
            for (int j = 0; j < 8; j++)
                #pragma unroll
                for (int r = 0; r < 4; r++) s[t][j][r] = 0.f;

        #pragma unroll
        for (int ks = 0; ks < 8; ks++) {
            uint32_t a0[4], a1[4];
            uint32_t qa = QH + a_row0 * FROWB + ks * 32 + a_kb;
            LDSM_X4(a0[0], a0[1], a0[2], a0[3], qa);
            LDSM_X4(a1[0], a1[1], a1[2], a1[3], qa + 16 * FROWB);
            #pragma unroll
            for (int bj = 0; bj < 4; bj++) {
                uint32_t ka = kb + (bj * 16 + b_row) * FROWB + ks * 32 + b_kb;
                uint32_t h0, h1, h2, h3;
                LDSM_X4(h0, h1, h2, h3, ka);
                uint32_t bh0[2] = {h0, h1}, bh1[2] = {h2, h3};
                mma16816h(s[0][2 * bj],     a0, bh0);
                mma16816h(s[0][2 * bj + 1], a0, bh1);
                mma16816h(s[1][2 * bj],     a1, bh0);
                mma16816h(s[1][2 * bj + 1], a1, bh1);
            }
        }

        // ---- causal mask (only last 4 tiles of the block) ----
        if (kt >= 4 * bi) {
            #pragma unroll
            for (int t = 0; t < 2; t++) {
                int row0 = q0 + wq * 32 + t * 16 + er, row1 = row0 + 8;
                int colb = kt * 64 + ec2;
                #pragma unroll
                for (int j = 0; j < 8; j++) {
                    int c0 = colb + j * 8, c1 = c0 + 1;
                    if (c0 > row0) s[t][j][0] = -1e30f;
                    if (c1 > row0) s[t][j][1] = -1e30f;
                    if (c0 > row1) s[t][j][2] = -1e30f;
                    if (c1 > row1) s[t][j][3] = -1e30f;
                }
            }
        }

        // ---- online softmax per ti + pack P ----
        uint32_t ph[2][16], pl[2][16];
        #pragma unroll
        for (int t = 0; t < 2; t++) {
            float mx0 = -1e30f, mx1 = -1e30f;
            #pragma unroll
            for (int j = 0; j < 8; j++) {
                mx0 = fmaxf(mx0, fmaxf(s[t][j][0], s[t][j][1]));
                mx1 = fmaxf(mx1, fmaxf(s[t][j][2], s[t][j][3]));
            }
            mx0 = fmaxf(mx0, __shfl_xor_sync(0xffffffffu, mx0, 1));
            mx0 = fmaxf(mx0, __shfl_xor_sync(0xffffffffu, mx0, 2));
            mx1 = fmaxf(mx1, __shfl_xor_sync(0xffffffffu, mx1, 1));
            mx1 = fmaxf(mx1, __shfl_xor_sync(0xffffffffu, mx1, 2));
            float mn0 = fmaxf(m[t][0], mx0), mn1 = fmaxf(m[t][1], mx1);
            float al0 = __expf(m[t][0] - mn0), al1 = __expf(m[t][1] - mn1);
            m[t][0] = mn0; m[t][1] = mn1;
            float sm0 = 0.f, sm1 = 0.f;
            #pragma unroll
            for (int j = 0; j < 8; j++) {
                s[t][j][0] = __expf(s[t][j][0] - mn0); sm0 += s[t][j][0];
                s[t][j][1] = __expf(s[t][j][1] - mn0); sm0 += s[t][j][1];
                s[t][j][2] = __expf(s[t][j][2] - mn1); sm1 += s[t][j][2];
                s[t][j][3] = __expf(s[t][j][3] - mn1); sm1 += s[t][j][3];
            }
            sm0 += __shfl_xor_sync(0xffffffffu, sm0, 1);
            sm0 += __shfl_xor_sync(0xffffffffu, sm0, 2);
            sm1 += __shfl_xor_sync(0xffffffffu, sm1, 1);
            sm1 += __shfl_xor_sync(0xffffffffu, sm1, 2);
            l[t][0] = l[t][0] * al0 + sm0;
            l[t][1] = l[t][1] * al1 + sm1;
            #pragma unroll
            for (int j = 0; j < 16; j++) {
                o[t][j][0] *= al0; o[t][j][1] *= al0;
                o[t][j][2] *= al1; o[t][j][3] *= al1;
            }
            #pragma unroll
            for (int ki = 0; ki < 4; ki++) {
                packhl_h(s[t][2 * ki][0],     s[t][2 * ki][1],
                         ph[t][ki * 4 + 0], pl[t][ki * 4 + 0]);
                packhl_h(s[t][2 * ki][2],     s[t][2 * ki][3],
                         ph[t][ki * 4 + 1], pl[t][ki * 4 + 1]);
                packhl_h(s[t][2 * ki + 1][0], s[t][2 * ki + 1][1],
                         ph[t][ki * 4 + 2], pl[t][ki * 4 + 2]);
                packhl_h(s[t][2 * ki + 1][2], s[t][2 * ki + 1][3],
                         ph[t][ki * 4 + 3], pl[t][ki * 4 + 3]);
            }
        }

        // ---- phase 2: O += P V; V frag shared across ti and hi/lo ----
        const uint32_t vbase = kb + FKBYTES;
        #pragma unroll
        for (int ki = 0; ki < 4; ki++) {
            #pragma unroll
            for (int nj = 0; nj < 8; nj++) {
                uint32_t va = vbase + (ki * 16 + v_row) * FROWB + nj * 32 + v_cb;
                uint32_t h0, h1, h2, h3;
                LDSM_X4T(h0, h1, h2, h3, va);
                uint32_t vh0[2] = {h0, h1}, vh1[2] = {h2, h3};
                mma16816h(o[0][2 * nj],     &ph[0][ki * 4], vh0);
                mma16816h(o[0][2 * nj + 1], &ph[0][ki * 4], vh1);
                mma16816h(o[1][2 * nj],     &ph[1][ki * 4], vh0);
                mma16816h(o[1][2 * nj + 1], &ph[1][ki * 4], vh1);
                mma16816h(o[0][2 * nj],     &pl[0][ki * 4], vh0);
                mma16816h(o[0][2 * nj + 1], &pl[0][ki * 4], vh1);
                mma16816h(o[1][2 * nj],     &pl[1][ki * 4], vh0);
                mma16816h(o[1][2 * nj + 1], &pl[1][ki * 4], vh1);
            }
        }
        __syncthreads();   // protect KV buffer before next produce overwrites
    }

    // ---- epilogue: normalize + single fp16 write ----
    #pragma unroll
    for (int t = 0; t < 2; t++) {
        float il0 = 1.f / l[t][0], il1 = 1.f / l[t][1];
        int row0 = q0 + wq * 32 + t * 16 + er;
        #pragma unroll
        for (int j = 0; j < 16; j++) {
            int col = hh * 128 + j * 8 + ec2;
            size_t off0 = ((size_t)b * S_ + row0) * D_ + col;
            size_t off1 = ((size_t)b * S_ + row0 + 8) * D_ + col;
            *(__half2*)(oh_ + off0) = __floats2half2_rn(o[t][j][0] * il0, o[t][j][1] * il0);
            *(__half2*)(oh_ + off1) = __floats2half2_rn(o[t][j][2] * il1, o[t][j][3] * il1);
        }
    }
}

// ---------------------------------------------------------------------------
// Launch
// ---------------------------------------------------------------------------
extern "C" void kernel_launch(void* const* d_in, const int* in_sizes, int n_in,
                              void* d_out, int out_size)
{
    (void)in_sizes; (void)n_in; (void)out_size;
    const float* x    = (const float*)d_in[0];
    const float* Wqkv = (const float*)d_in[1];
    const float* bqkv = (const float*)d_in[2];
    const float* Wo   = (const float*)d_in[3];
    const float* bo   = (const float*)d_in[4];
    float* out = (float*)d_out;

    __half *xh, *w1h, *w2h, *qh, *kh, *vh, *ah;
    cudaGetSymbolAddress((void**)&xh, g_xh);
    cudaGetSymbolAddress((void**)&w1h, g_w1h);   cudaGetSymbolAddress((void**)&w2h, g_w2h);
    cudaGetSymbolAddress((void**)&qh, g_qh);
    cudaGetSymbolAddress((void**)&kh, g_kh);     cudaGetSymbolAddress((void**)&vh, g_vh);
    cudaGetSymbolAddress((void**)&ah, g_ah);

    cudaFuncSetAttribute(gemm_qkv,
                         cudaFuncAttributeMaxDynamicSharedMemorySize, QKV_DYN_SMEM);
    cudaFuncSetAttribute(gemm_proj,
                         cudaFuncAttributeMaxDynamicSharedMemorySize, PROJ_DYN_SMEM);
    cudaFuncSetAttribute(flash_mma,
                         cudaFuncAttributeMaxDynamicSharedMemorySize, FLASH_DYN_SMEM);

    // 1) convert x to single fp16
    {
        int n4 = (M_ * D_) / 4;
        convert_f32_h<<<(n4 + 255) / 256, 256>>>(x, xh, n4);
    }
    // 2) transpose weights to [N,K] fp16
    transpose_h<<<dim3((3 * D_) / 32, D_ / 32), dim3(32, 8)>>>(Wqkv, w1h, D_, 3 * D_);
    transpose_h<<<dim3(D_ / 32, D_ / 32), dim3(32, 8)>>>(Wo, w2h, D_, D_);

    // 3) QKV GEMM (fp16x1, BN=192 -> 1024 CTAs)
    gemm_qkv<<<dim3((3 * D_) / 192, M_ / 128), 256, QKV_DYN_SMEM>>>(
        xh, w1h, bqkv, qh, kh, vh);

    // 4) HMMA flash attention (BQ=256, warp 32 q-rows)
    flash_mma<<<dim3(S_ / FBQ, H_, B_), 256, FLASH_DYN_SMEM>>>(
        qh, kh, vh, ah);

    // 5) out = attn @ Wo + bo  (fp16x1)
    gemm_proj<<<dim3(D_ / 256, M_ / 128), 256, PROJ_DYN_SMEM>>>(
        ah, w2h, bo, out);
}

// round 14
// speedup vs baseline: 1.1830x; 1.1830x over previous
#include <cuda_runtime.h>
#include <cuda_fp16.h>
#include <cstdint>
#include <cstddef>

// ---------------------------------------------------------------------------
// Problem constants
// ---------------------------------------------------------------------------
#define B_  2
#define S_  2048
#define D_  2048
#define H_  16
#define HD_ 128
#define M_  (B_*S_)            // 4096 rows
#define K_  2048               // inner dim of BOTH gemms (compile-time)
#define SCALE_ 0.08838834764831845f

// ---------------------------------------------------------------------------
// Scratch (__device__ globals; no allocation allowed)
// ---------------------------------------------------------------------------
__device__ __half g_xh[(size_t)M_ * D_];                // x single fp16
__device__ __half g_w1h[(size_t)3 * D_ * D_];           // Wqkv^T [6144,2048] fp16
__device__ __half g_w2h[(size_t)D_ * D_];               // Wo^T [2048,2048] fp16
// q (pre-scaled), k, v single fp16.  [B,H,S,HD]
__device__ __half g_qh[(size_t)M_ * D_];
__device__ __half g_kh[(size_t)M_ * D_];
__device__ __half g_vh[(size_t)M_ * D_];
// attention output [B,S,D] single fp16 (feeds proj)
__device__ __half g_ah[(size_t)M_ * D_];

// ---------------------------------------------------------------------------
// Portable PTX helpers (virtual arch compute_103: no tcgen05)
// ---------------------------------------------------------------------------
__device__ __forceinline__ uint32_t smem_u32(const void* p) {
    uint32_t a;
    asm("{ .reg .u64 t; cvta.to.shared.u64 t, %1; cvt.u32.u64 %0, t; }"
        : "=r"(a) : "l"(p));
    return a;
}

#define CP16(dst_u32, src_ptr) \
    asm volatile("cp.async.cg.shared.global [%0], [%1], 16;" \
                 :: "r"(dst_u32), "l"(src_ptr) : "memory")
#define CP_COMMIT() asm volatile("cp.async.commit_group;" ::: "memory")
#define CP_WAIT(n)  asm volatile("cp.async.wait_group %0;" :: "n"(n) : "memory")

#define LDSM_X4(r0, r1, r2, r3, addr) \
    asm volatile("ldmatrix.sync.aligned.m8n8.x4.shared.b16 {%0,%1,%2,%3}, [%4];" \
                 : "=r"(r0), "=r"(r1), "=r"(r2), "=r"(r3) : "r"(addr))
#define LDSM_X4T(r0, r1, r2, r3, addr) \
    asm volatile("ldmatrix.sync.aligned.m8n8.x4.trans.shared.b16 {%0,%1,%2,%3}, [%4];" \
                 : "=r"(r0), "=r"(r1), "=r"(r2), "=r"(r3) : "r"(addr))

__device__ __forceinline__ void mma16816h(float* d, const uint32_t* a,
                                          const uint32_t* b) {
    asm volatile(
        "mma.sync.aligned.m16n8k16.row.col.f32.f16.f16.f32 "
        "{%0,%1,%2,%3}, {%4,%5,%6,%7}, {%8,%9}, {%0,%1,%2,%3};"
        : "+f"(d[0]), "+f"(d[1]), "+f"(d[2]), "+f"(d[3])
        : "r"(a[0]), "r"(a[1]), "r"(a[2]), "r"(a[3]), "r"(b[0]), "r"(b[1]));
}

// ---------------------------------------------------------------------------
// convert / transpose pre-passes
// ---------------------------------------------------------------------------
__global__ void convert_f32_h(const float* __restrict__ in,
                              __half* __restrict__ out, int n4) {
    int i = blockIdx.x * blockDim.x + threadIdx.x;
    if (i >= n4) return;
    float4 v = *(const float4*)(in + (size_t)i * 4);
    __half2 a = __floats2half2_rn(v.x, v.y);
    __half2 b = __floats2half2_rn(v.z, v.w);
    __half2* op = (__half2*)(out + (size_t)i * 4);
    op[0] = a; op[1] = b;
}

__global__ void transpose_h(const float* __restrict__ W,
                            __half* __restrict__ Th, int K, int N) {
    __shared__ float t[32][33];
    int n0 = blockIdx.x * 32, k0 = blockIdx.y * 32;
    int tx = threadIdx.x, ty = threadIdx.y;      // (32,8)
    #pragma unroll
    for (int j = 0; j < 32; j += 8)
        t[ty + j][tx] = W[(size_t)(k0 + ty + j) * N + n0 + tx];
    __syncthreads();
    #pragma unroll
    for (int j = 0; j < 32; j += 8)
        Th[(size_t)(n0 + ty + j) * K + k0 + tx] = __float2half(t[tx][ty + j]);
}

// ---------------------------------------------------------------------------
// shared swizzle: 64B rows, chunk ^= (row>>1)&3
// ---------------------------------------------------------------------------
#define GBK 32
#define GSWZ(r, c) ((uint32_t)(r) * 64u + ((((uint32_t)(c) ^ (((uint32_t)(r) >> 1) & 3u))) << 4))

// ---------------------------------------------------------------------------
// QKV GEMM (fp16x1):  BM=128, BN=192, BK=32, 8 warps (2x4), warp 64x48,
// 4-stage cp.async.  Epilogue: bias (+scale for q); single fp16 q/k/v.
// ---------------------------------------------------------------------------
#define QOFF_A 0
#define QOFF_B 8192                   // A: 128 rows * 64B = 8192
#define QSTAGEB 20480                 // + B: 192 rows * 64B = 12288
#define QNSTAGE 4
#define QKV_DYN_SMEM (QNSTAGE * QSTAGEB)   // 81920

__global__ __launch_bounds__(256, 1) void gemm_qkv(
    const __half* __restrict__ Am, const __half* __restrict__ Bm,
    const float* __restrict__ bias,
    __half* __restrict__ qh, __half* __restrict__ kh, __half* __restrict__ vh)
{
    extern __shared__ __align__(128) char sm[];
    const uint32_t sbase = smem_u32(sm);

    const int tid = threadIdx.x;
    const int wid = tid >> 5;
    const int lane = tid & 31;
    const int m0 = blockIdx.y * 128;
    const int n0 = blockIdx.x * 192;
    const int wm = (wid >> 2) * 64;      // 0 / 64
    const int wn = (wid & 3) * 48;       // 0/48/96/144

    const int tr = tid >> 2;             // 0..63
    const int pc = tid & 3;              // chunk 0..3
    const __half* pA = Am + (m0 + tr) * K_ + pc * 8;
    const __half* pB = Bm + (n0 + tr) * K_ + pc * 8;
    const uint32_t dT0 = GSWZ(tr, pc);
    const uint32_t dT1 = GSWZ(tr + 64, pc);
    const uint32_t dT2 = GSWZ(tr + 128, pc);

    auto produce = [&](int stg, int kblk) {
        uint32_t s = sbase + stg * QSTAGEB;
        CP16(s + QOFF_A + dT0, pA + kblk);
        CP16(s + QOFF_A + dT1, pA + 64 * K_ + kblk);
        CP16(s + QOFF_B + dT0, pB + kblk);
        CP16(s + QOFF_B + dT1, pB + 64 * K_ + kblk);
        CP16(s + QOFF_B + dT2, pB + 128 * K_ + kblk);
    };

    float acc[4][6][4];
    #pragma unroll
    for (int i = 0; i < 4; i++)
        #pragma unroll
        for (int j = 0; j < 6; j++)
            #pragma unroll
            for (int r = 0; r < 4; r++) acc[i][j][r] = 0.f;

    uint32_t aoff[4], boff[3];
    #pragma unroll
    for (int ti = 0; ti < 4; ti++)
        aoff[ti] = GSWZ(wm + ti * 16 + (lane & 15), (lane >> 4));
    #pragma unroll
    for (int pj = 0; pj < 3; pj++)
        boff[pj] = GSWZ(wn + pj * 16 + (lane & 7) + ((lane >> 4) & 1) * 8,
                        ((lane >> 3) & 1));

    auto compute = [&](int stg) {
        uint32_t s = sbase + stg * QSTAGEB;
        #pragma unroll
        for (int ks = 0; ks < 2; ks++) {
            const uint32_t kx = ks ? 0x20u : 0u;
            uint32_t ah[4][4];
            #pragma unroll
            for (int ti = 0; ti < 4; ti++) {
                uint32_t ad = s + QOFF_A + (aoff[ti] ^ kx);
                LDSM_X4(ah[ti][0], ah[ti][1], ah[ti][2], ah[ti][3], ad);
            }
            #pragma unroll
            for (int pj = 0; pj < 3; pj++) {
                uint32_t bd = s + QOFF_B + (boff[pj] ^ kx);
                uint32_t h0, h1, h2, h3;
                LDSM_X4(h0, h1, h2, h3, bd);
                uint32_t bh0[2] = {h0, h1}, bh1[2] = {h2, h3};
                #pragma unroll
                for (int ti = 0; ti < 4; ti++) {
                    mma16816h(acc[ti][2 * pj],     ah[ti], bh0);
                    mma16816h(acc[ti][2 * pj + 1], ah[ti], bh1);
                }
            }
        }
    };

    const int NK = K_ / GBK;             // 64
    produce(0, 0); CP_COMMIT();
    produce(1, GBK); CP_COMMIT();
    produce(2, 2 * GBK); CP_COMMIT();

    for (int it = 0; it < NK; ++it) {
        CP_WAIT(2);
        __syncthreads();
        compute(it & (QNSTAGE - 1));
        if (it + 3 < NK) produce((it + 3) & (QNSTAGE - 1), (it + 3) * GBK);
        CP_COMMIT();
    }

    // ---- epilogue: single fp16 q (scaled) / k / v ----
    const int er = lane >> 2;
    const int ec = (lane & 3) * 2;
    #pragma unroll
    for (int tj = 0; tj < 6; tj++) {
        int col = n0 + wn + tj * 8 + ec;
        int hh = col / 384, rem = col % 384;
        int which = rem >> 7, hd = rem & 127;
        __half* dst = which == 0 ? qh : (which == 1 ? kh : vh);
        float sc = which == 0 ? SCALE_ : 1.0f;
        float bx = bias[col], by = bias[col + 1];
        #pragma unroll
        for (int ti = 0; ti < 4; ti++) {
            #pragma unroll
            for (int rr = 0; rr < 2; rr++) {
                int row = m0 + wm + ti * 16 + er + rr * 8;
                int bb = row >> 11, ss = row & 2047;
                size_t off = (((size_t)(bb * H_ + hh)) * S_ + ss) * HD_ + hd;
                float vx = (acc[ti][tj][rr * 2] + bx) * sc;
                float vy = (acc[ti][tj][rr * 2 + 1] + by) * sc;
                *(__half2*)(dst + off) = __floats2half2_rn(vx, vy);
            }
        }
    }
}

// ---------------------------------------------------------------------------
// Proj GEMM (fp16x1):  C = A @ Bt^T + bias.  A single fp16, B single fp16.
// BM=128, BN=256, BK=32, 8 warps (2x4), warp 64x64, 4-stage cp.async.
// ---------------------------------------------------------------------------
#define POFF_A 0
#define POFF_B 8192                   // A: 128 rows * 64B
#define PSTAGEB 24576                 // + B: 256 rows * 64B = 16384
#define PNSTAGE 4
#define PROJ_DYN_SMEM (PNSTAGE * PSTAGEB)   // 98304

__global__ __launch_bounds__(256, 1) void gemm_proj(
    const __half* __restrict__ Am, const __half* __restrict__ Bm,
    const float* __restrict__ bias, float* __restrict__ C)
{
    extern __shared__ __align__(128) char sm[];
    const uint32_t sbase = smem_u32(sm);

    const int tid = threadIdx.x;
    const int wid = tid >> 5;
    const int lane = tid & 31;
    const int m0 = blockIdx.y * 128;
    const int n0 = blockIdx.x * 256;
    const int wm = (wid >> 2) * 64;
    const int wn = (wid & 3) * 64;

    const int tr = tid >> 2;
    const int pc = tid & 3;
    const __half* pA = Am + (m0 + tr) * K_ + pc * 8;
    const __half* pB = Bm + (n0 + tr) * K_ + pc * 8;
    const uint32_t dT0 = GSWZ(tr, pc);
    const uint32_t dT1 = GSWZ(tr + 64, pc);
    const uint32_t dT2 = GSWZ(tr + 128, pc);
    const uint32_t dT3 = GSWZ(tr + 192, pc);

    auto produce = [&](int stg, int kblk) {
        uint32_t s = sbase + stg * PSTAGEB;
        CP16(s + POFF_A + dT0, pA + kblk);
        CP16(s + POFF_A + dT1, pA + 64 * K_ + kblk);
        CP16(s + POFF_B + dT0, pB + kblk);
        CP16(s + POFF_B + dT1, pB + 64 * K_ + kblk);
        CP16(s + POFF_B + dT2, pB + 128 * K_ + kblk);
        CP16(s + POFF_B + dT3, pB + 192 * K_ + kblk);
    };

    float acc[4][8][4];
    #pragma unroll
    for (int i = 0; i < 4; i++)
        #pragma unroll
        for (int j = 0; j < 8; j++)
            #pragma unroll
            for (int r = 0; r < 4; r++) acc[i][j][r] = 0.f;

    uint32_t aoff[4], boff[4];
    #pragma unroll
    for (int ti = 0; ti < 4; ti++)
        aoff[ti] = GSWZ(wm + ti * 16 + (lane & 15), (lane >> 4));
    #pragma unroll
    for (int pj = 0; pj < 4; pj++)
        boff[pj] = GSWZ(wn + pj * 16 + (lane & 7) + ((lane >> 4) & 1) * 8,
                        ((lane >> 3) & 1));

    auto compute = [&](int stg) {
        uint32_t s = sbase + stg * PSTAGEB;
        #pragma unroll
        for (int ks = 0; ks < 2; ks++) {
            const uint32_t kx = ks ? 0x20u : 0u;
            uint32_t ah[4][4];
            #pragma unroll
            for (int ti = 0; ti < 4; ti++) {
                uint32_t ad = s + POFF_A + (aoff[ti] ^ kx);
                LDSM_X4(ah[ti][0], ah[ti][1], ah[ti][2], ah[ti][3], ad);
            }
            #pragma unroll
            for (int pj = 0; pj < 4; pj++) {
                uint32_t bd = s + POFF_B + (boff[pj] ^ kx);
                uint32_t h0, h1, h2, h3;
                LDSM_X4(h0, h1, h2, h3, bd);
                uint32_t bh0[2] = {h0, h1}, bh1[2] = {h2, h3};
                #pragma unroll
                for (int ti = 0; ti < 4; ti++) {
                    mma16816h(acc[ti][2 * pj],     ah[ti], bh0);
                    mma16816h(acc[ti][2 * pj + 1], ah[ti], bh1);
                }
            }
        }
    };

    const int NK = K_ / GBK;
    produce(0, 0); CP_COMMIT();
    produce(1, GBK); CP_COMMIT();
    produce(2, 2 * GBK); CP_COMMIT();

    for (int it = 0; it < NK; ++it) {
        CP_WAIT(2);
        __syncthreads();
        compute(it & (PNSTAGE - 1));
        if (it + 3 < NK) produce((it + 3) & (PNSTAGE - 1), (it + 3) * GBK);
        CP_COMMIT();
    }

    const int er = lane >> 2;
    const int ec = (lane & 3) * 2;
    #pragma unroll
    for (int tj = 0; tj < 8; tj++) {
        int col = n0 + wn + tj * 8 + ec;
        float bx = bias[col], by = bias[col + 1];
        #pragma unroll
        for (int ti = 0; ti < 4; ti++) {
            int row = m0 + wm + ti * 16 + er;
            float2 v0 = { acc[ti][tj][0] + bx, acc[ti][tj][1] + by };
            float2 v1 = { acc[ti][tj][2] + bx, acc[ti][tj][3] + by };
            *(float2*)(C + (size_t)row * D_ + col) = v0;
            *(float2*)(C + (size_t)(row + 8) * D_ + col) = v1;
        }
    }
}

// ---------------------------------------------------------------------------
// HMMA causal flash attention: 4 warps/CTA, BQ=128 (warp = 32 q-rows, ti=2),
// 2 CTAs/SM.  Q/K single fp16 (1 term), P single fp16 x V single fp16
// (1 term).  K frag shared across ti (phase 1); V frag shared across ti
// (phase 2).  LDSM 80 / MMA 256 per warp-tile.  BKV=64, double buffer.
// ---------------------------------------------------------------------------
#define FROWB 272                      // 128 fp16 + 8 pad = 136 elems
#define FQBYTES (128 * FROWB)          // Q tile: 34816
#define FKBYTES (64 * FROWB)           // per K/V array: 17408
#define FSTGB (2 * FKBYTES)            // k, v: 34816
#define FLASH_DYN_SMEM (FQBYTES + 2 * FSTGB)   // 104448 B

__global__ __launch_bounds__(128, 2) void flash_mma(
    const __half* __restrict__ qh_,
    const __half* __restrict__ kh_, const __half* __restrict__ vh_,
    __half* __restrict__ oh_)
{
    extern __shared__ __align__(128) char fsm[];
    const uint32_t sb = smem_u32(fsm);
    const int tid = threadIdx.x, wq = tid >> 5, lane = tid & 31;
    const int bi = (int)gridDim.x - 1 - (int)blockIdx.x;   // big blocks first
    const int hh = blockIdx.y, b = blockIdx.z;
    const int q0 = bi * 128;
    const size_t bh = ((size_t)b * H_ + hh) * S_;
    const uint32_t QH = sb;
    const uint32_t KV0 = sb + FQBYTES;

    // Q tile load: 128 rows x 16 chunks, 128 threads -> 16 CP16/thread
    #pragma unroll
    for (int i = 0; i < 16; i++) {
        int id = tid + i * 128;
        int r = id >> 4, c = id & 15;
        size_t src = (bh + q0 + r) * HD_ + c * 8;
        CP16(QH + r * FROWB + c * 16, qh_ + src);
    }
    auto produce = [&](int stg, int kt) {
        uint32_t s = KV0 + stg * FSTGB;
        int k0 = kt * 64;
        #pragma unroll
        for (int i = 0; i < 8; i++) {
            int id = tid + i * 128;
            int r = id >> 4, c = id & 15;
            size_t src = (bh + k0 + r) * HD_ + c * 8;
            uint32_t d = r * FROWB + c * 16;
            CP16(s + d, kh_ + src);
            CP16(s + FKBYTES + d, vh_ + src);
        }
    };

    float o[2][16][4];
    #pragma unroll
    for (int t = 0; t < 2; t++)
        #pragma unroll
        for (int j = 0; j < 16; j++)
            #pragma unroll
            for (int r = 0; r < 4; r++) o[t][j][r] = 0.f;
    float m[2][2] = {{-1e30f, -1e30f}, {-1e30f, -1e30f}};
    float l[2][2] = {{0.f, 0.f}, {0.f, 0.f}};

    const int er = lane >> 2, ec2 = (lane & 3) * 2;
    const uint32_t a_row0 = wq * 32 + (lane & 15);   // ti=0; ti=1: +16 rows
    const uint32_t a_kb  = (lane >> 4) * 16;
    const uint32_t b_row = (lane & 7) + ((lane >> 4) & 1) * 8;
    const uint32_t b_kb  = ((lane >> 3) & 1) * 16;
    const uint32_t v_row = (lane & 7) + ((lane >> 3) & 1) * 8;
    const uint32_t v_cb  = ((lane >> 4) & 1) * 16;

    const int nkt = 2 * bi + 2;
    produce(0, 0);
    CP_COMMIT();

    for (int kt = 0; kt < nkt; kt++) {
        if (kt + 1 < nkt) { produce((kt + 1) & 1, kt + 1); CP_COMMIT(); CP_WAIT(1); }
        else CP_WAIT(0);
        __syncthreads();
        const uint32_t kb = KV0 + (kt & 1) * FSTGB;

        // ---- phase 1: S = Q K^T for both ti; K fragment shared ----
        float s[2][8][4];
        #pragma unroll
        for (int t = 0; t < 2; t++)
            #pragma unroll
            for (int j = 0; j < 8; j++)
                #pragma unroll
                for (int r = 0; r < 4; r++) s[t][j][r] = 0.f;

        #pragma unroll
        for (int ks = 0; ks < 8; ks++) {
            uint32_t a0[4], a1[4];
            uint32_t qa = QH + a_row0 * FROWB + ks * 32 + a_kb;
            LDSM_X4(a0[0], a0[1], a0[2], a0[3], qa);
            LDSM_X4(a1[0], a1[1], a1[2], a1[3], qa + 16 * FROWB);
            #pragma unroll
            for (int bj = 0; bj < 4; bj++) {
                uint32_t ka = kb + (bj * 16 + b_row) * FROWB + ks * 32 + b_kb;
                uint32_t h0, h1, h2, h3;
                LDSM_X4(h0, h1, h2, h3, ka);
                uint32_t bh0[2] = {h0, h1}, bh1[2] = {h2, h3};
                mma16816h(s[0][2 * bj],     a0, bh0);
                mma16816h(s[0][2 * bj + 1], a0, bh1);
                mma16816h(s[1][2 * bj],     a1, bh0);
                mma16816h(s[1][2 * bj + 1], a1, bh1);
            }
        }

        // ---- causal mask (only last two tiles of this block) ----
        if (kt >= 2 * bi) {
            #pragma unroll
            for (int t = 0; t < 2; t++) {
                int row0 = q0 + wq * 32 + t * 16 + er, row1 = row0 + 8;
                int colb = kt * 64 + ec2;
                #pragma unroll
                for (int j = 0; j < 8; j++) {
                    int c0 = colb + j * 8, c1 = c0 + 1;
                    if (c0 > row0) s[t][j][0] = -1e30f;
                    if (c1 > row0) s[t][j][1] = -1e30f;
                    if (c0 > row1) s[t][j][2] = -1e30f;
                    if (c1 > row1) s[t][j][3] = -1e30f;
                }
            }
        }

        // ---- online softmax per ti; pack P (single fp16) in place ----
        uint32_t ph[2][16];
        #pragma unroll
        for (int t = 0; t < 2; t++) {
            float mx0 = -1e30f, mx1 = -1e30f;
            #pragma unroll
            for (int j = 0; j < 8; j++) {
                mx0 = fmaxf(mx0, fmaxf(s[t][j][0], s[t][j][1]));
                mx1 = fmaxf(mx1, fmaxf(s[t][j][2], s[t][j][3]));
            }
            mx0 = fmaxf(mx0, __shfl_xor_sync(0xffffffffu, mx0, 1));
            mx0 = fmaxf(mx0, __shfl_xor_sync(0xffffffffu, mx0, 2));
            mx1 = fmaxf(mx1, __shfl_xor_sync(0xffffffffu, mx1, 1));
            mx1 = fmaxf(mx1, __shfl_xor_sync(0xffffffffu, mx1, 2));
            float mn0 = fmaxf(m[t][0], mx0), mn1 = fmaxf(m[t][1], mx1);
            float al0 = __expf(m[t][0] - mn0), al1 = __expf(m[t][1] - mn1);
            m[t][0] = mn0; m[t][1] = mn1;
            float sm0 = 0.f, sm1 = 0.f;
            #pragma unroll
            for (int j = 0; j < 8; j++) {
                s[t][j][0] = __expf(s[t][j][0] - mn0); sm0 += s[t][j][0];
                s[t][j][1] = __expf(s[t][j][1] - mn0); sm0 += s[t][j][1];
                s[t][j][2] = __expf(s[t][j][2] - mn1); sm1 += s[t][j][2];
                s[t][j][3] = __expf(s[t][j][3] - mn1); sm1 += s[t][j][3];
            }
            sm0 += __shfl_xor_sync(0xffffffffu, sm0, 1);
            sm0 += __shfl_xor_sync(0xffffffffu, sm0, 2);
            sm1 += __shfl_xor_sync(0xffffffffu, sm1, 1);
            sm1 += __shfl_xor_sync(0xffffffffu, sm1, 2);
            l[t][0] = l[t][0] * al0 + sm0;
            l[t][1] = l[t][1] * al1 + sm1;
            #pragma unroll
            for (int j = 0; j < 16; j++) {
                o[t][j][0] *= al0; o[t][j][1] *= al0;
                o[t][j][2] *= al1; o[t][j][3] *= al1;
            }
            // pack P rows into fp16x2 fragments (A-operand layout)
            #pragma unroll
            for (int ki = 0; ki < 4; ki++) {
                __half2 p0 = __floats2half2_rn(s[t][2 * ki][0],     s[t][2 * ki][1]);
                __half2 p1 = __floats2half2_rn(s[t][2 * ki][2],     s[t][2 * ki][3]);
                __half2 p2 = __floats2half2_rn(s[t][2 * ki + 1][0], s[t][2 * ki + 1][1]);
                __half2 p3 = __floats2half2_rn(s[t][2 * ki + 1][2], s[t][2 * ki + 1][3]);
                ph[t][ki * 4 + 0] = *reinterpret_cast<uint32_t*>(&p0);
                ph[t][ki * 4 + 1] = *reinterpret_cast<uint32_t*>(&p1);
                ph[t][ki * 4 + 2] = *reinterpret_cast<uint32_t*>(&p2);
                ph[t][ki * 4 + 3] = *reinterpret_cast<uint32_t*>(&p3);
            }
        }

        // ---- phase 2: O += P V; V fragment shared across both ti ----
        const uint32_t vbase = kb + FKBYTES;
        #pragma unroll
        for (int ki = 0; ki < 4; ki++) {
            #pragma unroll
            for (int nj = 0; nj < 8; nj++) {
                uint32_t va = vbase + (ki * 16 + v_row) * FROWB + nj * 32 + v_cb;
                uint32_t h0, h1, h2, h3;
                LDSM_X4T(h0, h1, h2, h3, va);
                uint32_t vh0[2] = {h0, h1}, vh1[2] = {h2, h3};
                mma16816h(o[0][2 * nj],     &ph[0][ki * 4], vh0);
                mma16816h(o[0][2 * nj + 1], &ph[0][ki * 4], vh1);
                mma16816h(o[1][2 * nj],     &ph[1][ki * 4], vh0);
                mma16816h(o[1][2 * nj + 1], &ph[1][ki * 4], vh1);
            }
        }
        __syncthreads();   // protect KV buffer before next produce overwrites
    }

    // ---- epilogue: normalize + single fp16 write ----
    #pragma unroll
    for (int t = 0; t < 2; t++) {
        float il0 = 1.f / l[t][0], il1 = 1.f / l[t][1];
        int row0 = q0 + wq * 32 + t * 16 + er;
        #pragma unroll
        for (int j = 0; j < 16; j++) {
            int col = hh * 128 + j * 8 + ec2;
            size_t off0 = ((size_t)b * S_ + row0) * D_ + col;
            size_t off1 = ((size_t)b * S_ + row0 + 8) * D_ + col;
            *(__half2*)(oh_ + off0) = __floats2half2_rn(o[t][j][0] * il0, o[t][j][1] * il0);
            *(__half2*)(oh_ + off1) = __floats2half2_rn(o[t][j][2] * il1, o[t][j][3] * il1);
        }
    }
}

// ---------------------------------------------------------------------------
// Launch
// ---------------------------------------------------------------------------
extern "C" void kernel_launch(void* const* d_in, const int* in_sizes, int n_in,
                              void* d_out, int out_size)
{
    (void)in_sizes; (void)n_in; (void)out_size;
    const float* x    = (const float*)d_in[0];
    const float* Wqkv = (const float*)d_in[1];
    const float* bqkv = (const float*)d_in[2];
    const float* Wo   = (const float*)d_in[3];
    const float* bo   = (const float*)d_in[4];
    float* out = (float*)d_out;

    __half *xh, *w1h, *w2h, *qh, *kh, *vh, *ah;
    cudaGetSymbolAddress((void**)&xh, g_xh);
    cudaGetSymbolAddress((void**)&w1h, g_w1h);   cudaGetSymbolAddress((void**)&w2h, g_w2h);
    cudaGetSymbolAddress((void**)&qh, g_qh);
    cudaGetSymbolAddress((void**)&kh, g_kh);     cudaGetSymbolAddress((void**)&vh, g_vh);
    cudaGetSymbolAddress((void**)&ah, g_ah);

    cudaFuncSetAttribute(gemm_qkv,
                         cudaFuncAttributeMaxDynamicSharedMemorySize, QKV_DYN_SMEM);
    cudaFuncSetAttribute(gemm_proj,
                         cudaFuncAttributeMaxDynamicSharedMemorySize, PROJ_DYN_SMEM);
    cudaFuncSetAttribute(flash_mma,
                         cudaFuncAttributeMaxDynamicSharedMemorySize, FLASH_DYN_SMEM);

    // 1) convert x to single fp16
    {
        int n4 = (M_ * D_) / 4;
        convert_f32_h<<<(n4 + 255) / 256, 256>>>(x, xh, n4);
    }
    // 2) transpose weights to [N,K] fp16
    transpose_h<<<dim3((3 * D_) / 32, D_ / 32), dim3(32, 8)>>>(Wqkv, w1h, D_, 3 * D_);
    transpose_h<<<dim3(D_ / 32, D_ / 32), dim3(32, 8)>>>(Wo, w2h, D_, D_);

    // 3) QKV GEMM (fp16x1, BN=192 -> 1024 CTAs)
    gemm_qkv<<<dim3((3 * D_) / 192, M_ / 128), 256, QKV_DYN_SMEM>>>(
        xh, w1h, bqkv, qh, kh, vh);

    // 4) HMMA flash attention (4 warps, BQ=128, 2 CTAs/SM)
    flash_mma<<<dim3(S_ / 128, H_, B_), 128, FLASH_DYN_SMEM>>>(
        qh, kh, vh, ah);

    // 5) out = attn @ Wo + bo  (fp16x1)
    gemm_proj<<<dim3(D_ / 256, M_ / 128), 256, PROJ_DYN_SMEM>>>(
        ah, w2h, bo, out);
}

// round 17
// speedup vs baseline: 1.2502x; 1.0568x over previous
#include <cuda_runtime.h>
#include <cuda_fp16.h>
#include <cstdint>
#include <cstddef>

// ---------------------------------------------------------------------------
// Problem constants
// ---------------------------------------------------------------------------
#define B_  2
#define S_  2048
#define D_  2048
#define H_  16
#define HD_ 128
#define M_  (B_*S_)            // 4096 rows
#define K_  2048               // inner dim of BOTH gemms (compile-time)
#define SCALE_ 0.08838834764831845f

// ---------------------------------------------------------------------------
// Scratch (__device__ globals; no allocation allowed)
// ---------------------------------------------------------------------------
__device__ __half g_xh[(size_t)M_ * D_];                // x single fp16
__device__ __half g_w1h[(size_t)3 * D_ * D_];           // Wqkv^T [6144,2048] fp16
__device__ __half g_w2h[(size_t)D_ * D_];               // Wo^T [2048,2048] fp16
// q (pre-scaled), k, v single fp16.  [B,H,S,HD]
__device__ __half g_qh[(size_t)M_ * D_];
__device__ __half g_kh[(size_t)M_ * D_];
__device__ __half g_vh[(size_t)M_ * D_];
// attention output [B,S,D] single fp16 (feeds proj)
__device__ __half g_ah[(size_t)M_ * D_];

// ---------------------------------------------------------------------------
// Portable PTX helpers (virtual arch compute_103: no tcgen05)
// ---------------------------------------------------------------------------
__device__ __forceinline__ uint32_t smem_u32(const void* p) {
    uint32_t a;
    asm("{ .reg .u64 t; cvta.to.shared.u64 t, %1; cvt.u32.u64 %0, t; }"
        : "=r"(a) : "l"(p));
    return a;
}

#define CP16(dst_u32, src_ptr) \
    asm volatile("cp.async.cg.shared.global [%0], [%1], 16;" \
                 :: "r"(dst_u32), "l"(src_ptr) : "memory")
#define CP_COMMIT() asm volatile("cp.async.commit_group;" ::: "memory")
#define CP_WAIT(n)  asm volatile("cp.async.wait_group %0;" :: "n"(n) : "memory")

#define LDSM_X4(r0, r1, r2, r3, addr) \
    asm volatile("ldmatrix.sync.aligned.m8n8.x4.shared.b16 {%0,%1,%2,%3}, [%4];" \
                 : "=r"(r0), "=r"(r1), "=r"(r2), "=r"(r3) : "r"(addr))
#define LDSM_X4T(r0, r1, r2, r3, addr) \
    asm volatile("ldmatrix.sync.aligned.m8n8.x4.trans.shared.b16 {%0,%1,%2,%3}, [%4];" \
                 : "=r"(r0), "=r"(r1), "=r"(r2), "=r"(r3) : "r"(addr))

__device__ __forceinline__ void mma16816h(float* d, const uint32_t* a,
                                          const uint32_t* b) {
    asm volatile(
        "mma.sync.aligned.m16n8k16.row.col.f32.f16.f16.f32 "
        "{%0,%1,%2,%3}, {%4,%5,%6,%7}, {%8,%9}, {%0,%1,%2,%3};"
        : "+f"(d[0]), "+f"(d[1]), "+f"(d[2]), "+f"(d[3])
        : "r"(a[0]), "r"(a[1]), "r"(a[2]), "r"(a[3]), "r"(b[0]), "r"(b[1]));
}

// ---------------------------------------------------------------------------
// convert / transpose pre-passes
// ---------------------------------------------------------------------------
__global__ void convert_f32_h(const float* __restrict__ in,
                              __half* __restrict__ out, int n4) {
    int i = blockIdx.x * blockDim.x + threadIdx.x;
    if (i >= n4) return;
    float4 v = *(const float4*)(in + (size_t)i * 4);
    __half2 a = __floats2half2_rn(v.x, v.y);
    __half2 b = __floats2half2_rn(v.z, v.w);
    __half2* op = (__half2*)(out + (size_t)i * 4);
    op[0] = a; op[1] = b;
}

__global__ void transpose_h(const float* __restrict__ W,
                            __half* __restrict__ Th, int K, int N) {
    __shared__ float t[32][33];
    int n0 = blockIdx.x * 32, k0 = blockIdx.y * 32;
    int tx = threadIdx.x, ty = threadIdx.y;      // (32,8)
    #pragma unroll
    for (int j = 0; j < 32; j += 8)
        t[ty + j][tx] = W[(size_t)(k0 + ty + j) * N + n0 + tx];
    __syncthreads();
    #pragma unroll
    for (int j = 0; j < 32; j += 8)
        Th[(size_t)(n0 + ty + j) * K + k0 + tx] = __float2half(t[tx][ty + j]);
}

// ---------------------------------------------------------------------------
// shared swizzle: 64B rows, chunk ^= (row>>1)&3
// ---------------------------------------------------------------------------
#define GBK 32
#define GSWZ(r, c) ((uint32_t)(r) * 64u + ((((uint32_t)(c) ^ (((uint32_t)(r) >> 1) & 3u))) << 4))

// ---------------------------------------------------------------------------
// QKV GEMM (fp16x1):  BM=128, BN=96, BK=32, 4 warps (2x2, warp 64x48),
// 2 CTAs/SM, 4-stage cp.async.  Epilogue: bias (+scale for q); fp16 q/k/v.
// Grid 64x32 = 2048 CTAs -> 6.92 waves of 296 (98.8% wave util).
// ---------------------------------------------------------------------------
#define QOFF_A 0
#define QOFF_B 8192                   // A: 128 rows * 64B = 8192
#define QSTAGEB 14336                 // + B: 96 rows * 64B = 6144
#define QNSTAGE 4
#define QKV_DYN_SMEM (QNSTAGE * QSTAGEB)   // 57344 (x2 CTAs = 114688/SM)

__global__ __launch_bounds__(128, 2) void gemm_qkv(
    const __half* __restrict__ Am, const __half* __restrict__ Bm,
    const float* __restrict__ bias,
    __half* __restrict__ qh, __half* __restrict__ kh, __half* __restrict__ vh)
{
    extern __shared__ __align__(128) char sm[];
    const uint32_t sbase = smem_u32(sm);

    const int tid = threadIdx.x;
    const int wid = tid >> 5;            // 0..3
    const int lane = tid & 31;
    const int m0 = blockIdx.y * 128;
    const int n0 = blockIdx.x * 96;
    const int wm = (wid >> 1) * 64;      // 0 / 64
    const int wn = (wid & 1) * 48;       // 0 / 48

    const int tr = tid >> 2;             // 0..31
    const int pc = tid & 3;              // chunk 0..3
    const __half* pA = Am + (m0 + tr) * K_ + pc * 8;
    const __half* pB = Bm + (n0 + tr) * K_ + pc * 8;
    const uint32_t dA0 = GSWZ(tr, pc);
    const uint32_t dA1 = GSWZ(tr + 32, pc);
    const uint32_t dA2 = GSWZ(tr + 64, pc);
    const uint32_t dA3 = GSWZ(tr + 96, pc);

    auto produce = [&](int stg, int kblk) {
        uint32_t s = sbase + stg * QSTAGEB;
        CP16(s + QOFF_A + dA0, pA + kblk);
        CP16(s + QOFF_A + dA1, pA + 32 * K_ + kblk);
        CP16(s + QOFF_A + dA2, pA + 64 * K_ + kblk);
        CP16(s + QOFF_A + dA3, pA + 96 * K_ + kblk);
        CP16(s + QOFF_B + dA0, pB + kblk);
        CP16(s + QOFF_B + dA1, pB + 32 * K_ + kblk);
        CP16(s + QOFF_B + dA2, pB + 64 * K_ + kblk);
    };

    float acc[4][6][4];
    #pragma unroll
    for (int i = 0; i < 4; i++)
        #pragma unroll
        for (int j = 0; j < 6; j++)
            #pragma unroll
            for (int r = 0; r < 4; r++) acc[i][j][r] = 0.f;

    uint32_t aoff[4], boff[3];
    #pragma unroll
    for (int ti = 0; ti < 4; ti++)
        aoff[ti] = GSWZ(wm + ti * 16 + (lane & 15), (lane >> 4));
    #pragma unroll
    for (int pj = 0; pj < 3; pj++)
        boff[pj] = GSWZ(wn + pj * 16 + (lane & 7) + ((lane >> 4) & 1) * 8,
                        ((lane >> 3) & 1));

    auto compute = [&](int stg) {
        uint32_t s = sbase + stg * QSTAGEB;
        #pragma unroll
        for (int ks = 0; ks < 2; ks++) {
            const uint32_t kx = ks ? 0x20u : 0u;
            uint32_t ah[4][4];
            #pragma unroll
            for (int ti = 0; ti < 4; ti++) {
                uint32_t ad = s + QOFF_A + (aoff[ti] ^ kx);
                LDSM_X4(ah[ti][0], ah[ti][1], ah[ti][2], ah[ti][3], ad);
            }
            #pragma unroll
            for (int pj = 0; pj < 3; pj++) {
                uint32_t bd = s + QOFF_B + (boff[pj] ^ kx);
                uint32_t h0, h1, h2, h3;
                LDSM_X4(h0, h1, h2, h3, bd);
                uint32_t bh0[2] = {h0, h1}, bh1[2] = {h2, h3};
                #pragma unroll
                for (int ti = 0; ti < 4; ti++) {
                    mma16816h(acc[ti][2 * pj],     ah[ti], bh0);
                    mma16816h(acc[ti][2 * pj + 1], ah[ti], bh1);
                }
            }
        }
    };

    const int NK = K_ / GBK;             // 64
    produce(0, 0); CP_COMMIT();
    produce(1, GBK); CP_COMMIT();
    produce(2, 2 * GBK); CP_COMMIT();

    for (int it = 0; it < NK; ++it) {
        CP_WAIT(2);
        __syncthreads();
        compute(it & (QNSTAGE - 1));
        if (it + 3 < NK) produce((it + 3) & (QNSTAGE - 1), (it + 3) * GBK);
        CP_COMMIT();
    }

    // ---- epilogue: single fp16 q (scaled) / k / v ----
    const int er = lane >> 2;
    const int ec = (lane & 3) * 2;
    #pragma unroll
    for (int tj = 0; tj < 6; tj++) {
        int col = n0 + wn + tj * 8 + ec;
        int hh = col / 384, rem = col % 384;
        int which = rem >> 7, hd = rem & 127;
        __half* dst = which == 0 ? qh : (which == 1 ? kh : vh);
        float sc = which == 0 ? SCALE_ : 1.0f;
        float bx = bias[col], by = bias[col + 1];
        #pragma unroll
        for (int ti = 0; ti < 4; ti++) {
            #pragma unroll
            for (int rr = 0; rr < 2; rr++) {
                int row = m0 + wm + ti * 16 + er + rr * 8;
                int bb = row >> 11, ss = row & 2047;
                size_t off = (((size_t)(bb * H_ + hh)) * S_ + ss) * HD_ + hd;
                float vx = (acc[ti][tj][rr * 2] + bx) * sc;
                float vy = (acc[ti][tj][rr * 2 + 1] + by) * sc;
                *(__half2*)(dst + off) = __floats2half2_rn(vx, vy);
            }
        }
    }
}

// ---------------------------------------------------------------------------
// Proj GEMM (fp16x1):  C = A @ Bt^T + bias.  BM=128, BN=256, BK=32,
// 8 warps (2x4), warp 64x64, 4-stage cp.async.  (R14 proven version.)
// ---------------------------------------------------------------------------
#define POFF_A 0
#define POFF_B 8192                   // A: 128 rows * 64B
#define PSTAGEB 24576                 // + B: 256 rows * 64B = 16384
#define PNSTAGE 4
#define PROJ_DYN_SMEM (PNSTAGE * PSTAGEB)   // 98304

__global__ __launch_bounds__(256, 1) void gemm_proj(
    const __half* __restrict__ Am, const __half* __restrict__ Bm,
    const float* __restrict__ bias, float* __restrict__ C)
{
    extern __shared__ __align__(128) char sm[];
    const uint32_t sbase = smem_u32(sm);

    const int tid = threadIdx.x;
    const int wid = tid >> 5;
    const int lane = tid & 31;
    const int m0 = blockIdx.y * 128;
    const int n0 = blockIdx.x * 256;
    const int wm = (wid >> 2) * 64;
    const int wn = (wid & 3) * 64;

    const int tr = tid >> 2;
    const int pc = tid & 3;
    const __half* pA = Am + (m0 + tr) * K_ + pc * 8;
    const __half* pB = Bm + (n0 + tr) * K_ + pc * 8;
    const uint32_t dT0 = GSWZ(tr, pc);
    const uint32_t dT1 = GSWZ(tr + 64, pc);
    const uint32_t dT2 = GSWZ(tr + 128, pc);
    const uint32_t dT3 = GSWZ(tr + 192, pc);

    auto produce = [&](int stg, int kblk) {
        uint32_t s = sbase + stg * PSTAGEB;
        CP16(s + POFF_A + dT0, pA + kblk);
        CP16(s + POFF_A + dT1, pA + 64 * K_ + kblk);
        CP16(s + POFF_B + dT0, pB + kblk);
        CP16(s + POFF_B + dT1, pB + 64 * K_ + kblk);
        CP16(s + POFF_B + dT2, pB + 128 * K_ + kblk);
        CP16(s + POFF_B + dT3, pB + 192 * K_ + kblk);
    };

    float acc[4][8][4];
    #pragma unroll
    for (int i = 0; i < 4; i++)
        #pragma unroll
        for (int j = 0; j < 8; j++)
            #pragma unroll
            for (int r = 0; r < 4; r++) acc[i][j][r] = 0.f;

    uint32_t aoff[4], boff[4];
    #pragma unroll
    for (int ti = 0; ti < 4; ti++)
        aoff[ti] = GSWZ(wm + ti * 16 + (lane & 15), (lane >> 4));
    #pragma unroll
    for (int pj = 0; pj < 4; pj++)
        boff[pj] = GSWZ(wn + pj * 16 + (lane & 7) + ((lane >> 4) & 1) * 8,
                        ((lane >> 3) & 1));

    auto compute = [&](int stg) {
        uint32_t s = sbase + stg * PSTAGEB;
        #pragma unroll
        for (int ks = 0; ks < 2; ks++) {
            const uint32_t kx = ks ? 0x20u : 0u;
            uint32_t ah[4][4];
            #pragma unroll
            for (int ti = 0; ti < 4; ti++) {
                uint32_t ad = s + POFF_A + (aoff[ti] ^ kx);
                LDSM_X4(ah[ti][0], ah[ti][1], ah[ti][2], ah[ti][3], ad);
            }
            #pragma unroll
            for (int pj = 0; pj < 4; pj++) {
                uint32_t bd = s + POFF_B + (boff[pj] ^ kx);
                uint32_t h0, h1, h2, h3;
                LDSM_X4(h0, h1, h2, h3, bd);
                uint32_t bh0[2] = {h0, h1}, bh1[2] = {h2, h3};
                #pragma unroll
                for (int ti = 0; ti < 4; ti++) {
                    mma16816h(acc[ti][2 * pj],     ah[ti], bh0);
                    mma16816h(acc[ti][2 * pj + 1], ah[ti], bh1);
                }
            }
        }
    };

    const int NK = K_ / GBK;
    produce(0, 0); CP_COMMIT();
    produce(1, GBK); CP_COMMIT();
    produce(2, 2 * GBK); CP_COMMIT();

    for (int it = 0; it < NK; ++it) {
        CP_WAIT(2);
        __syncthreads();
        compute(it & (PNSTAGE - 1));
        if (it + 3 < NK) produce((it + 3) & (PNSTAGE - 1), (it + 3) * GBK);
        CP_COMMIT();
    }

    const int er = lane >> 2;
    const int ec = (lane & 3) * 2;
    #pragma unroll
    for (int tj = 0; tj < 8; tj++) {
        int col = n0 + wn + tj * 8 + ec;
        float bx = bias[col], by = bias[col + 1];
        #pragma unroll
        for (int ti = 0; ti < 4; ti++) {
            int row = m0 + wm + ti * 16 + er;
            float2 v0 = { acc[ti][tj][0] + bx, acc[ti][tj][1] + by };
            float2 v1 = { acc[ti][tj][2] + bx, acc[ti][tj][3] + by };
            *(float2*)(C + (size_t)row * D_ + col) = v0;
            *(float2*)(C + (size_t)(row + 8) * D_ + col) = v1;
        }
    }
}

// ---------------------------------------------------------------------------
// HMMA causal flash attention: 4 warps/CTA, BQ=128 (warp = 32 q-rows, ti=2),
// 2 CTAs/SM.  Q/K single fp16, P single fp16 x V single fp16.
// (R14 proven version: all LDSM after the barrier.)
// ---------------------------------------------------------------------------
#define FROWB 272                      // 128 fp16 + 8 pad = 136 elems
#define FQBYTES (128 * FROWB)          // Q tile: 34816
#define FKBYTES (64 * FROWB)           // per K/V array: 17408
#define FSTGB (2 * FKBYTES)            // k, v: 34816
#define FLASH_DYN_SMEM (FQBYTES + 2 * FSTGB)   // 104448 B

__global__ __launch_bounds__(128, 2) void flash_mma(
    const __half* __restrict__ qh_,
    const __half* __restrict__ kh_, const __half* __restrict__ vh_,
    __half* __restrict__ oh_)
{
    extern __shared__ __align__(128) char fsm[];
    const uint32_t sb = smem_u32(fsm);
    const int tid = threadIdx.x, wq = tid >> 5, lane = tid & 31;
    const int bi = (int)gridDim.x - 1 - (int)blockIdx.x;   // big blocks first
    const int hh = blockIdx.y, b = blockIdx.z;
    const int q0 = bi * 128;
    const size_t bh = ((size_t)b * H_ + hh) * S_;
    const uint32_t QH = sb;
    const uint32_t KV0 = sb + FQBYTES;

    // Q tile load: 128 rows x 16 chunks, 128 threads -> 16 CP16/thread
    #pragma unroll
    for (int i = 0; i < 16; i++) {
        int id = tid + i * 128;
        int r = id >> 4, c = id & 15;
        size_t src = (bh + q0 + r) * HD_ + c * 8;
        CP16(QH + r * FROWB + c * 16, qh_ + src);
    }
    auto produce = [&](int stg, int kt) {
        uint32_t s = KV0 + stg * FSTGB;
        int k0 = kt * 64;
        #pragma unroll
        for (int i = 0; i < 8; i++) {
            int id = tid + i * 128;
            int r = id >> 4, c = id & 15;
            size_t src = (bh + k0 + r) * HD_ + c * 8;
            uint32_t d = r * FROWB + c * 16;
            CP16(s + d, kh_ + src);
            CP16(s + FKBYTES + d, vh_ + src);
        }
    };

    float o[2][16][4];
    #pragma unroll
    for (int t = 0; t < 2; t++)
        #pragma unroll
        for (int j = 0; j < 16; j++)
            #pragma unroll
            for (int r = 0; r < 4; r++) o[t][j][r] = 0.f;
    float m[2][2] = {{-1e30f, -1e30f}, {-1e30f, -1e30f}};
    float l[2][2] = {{0.f, 0.f}, {0.f, 0.f}};

    const int er = lane >> 2, ec2 = (lane & 3) * 2;
    const uint32_t a_row0 = wq * 32 + (lane & 15);   // ti=0; ti=1: +16 rows
    const uint32_t a_kb  = (lane >> 4) * 16;
    const uint32_t b_row = (lane & 7) + ((lane >> 4) & 1) * 8;
    const uint32_t b_kb  = ((lane >> 3) & 1) * 16;
    const uint32_t v_row = (lane & 7) + ((lane >> 3) & 1) * 8;
    const uint32_t v_cb  = ((lane >> 4) & 1) * 16;

    const int nkt = 2 * bi + 2;
    produce(0, 0);
    CP_COMMIT();

    for (int kt = 0; kt < nkt; kt++) {
        if (kt + 1 < nkt) { produce((kt + 1) & 1, kt + 1); CP_COMMIT(); CP_WAIT(1); }
        else CP_WAIT(0);
        __syncthreads();
        const uint32_t kb = KV0 + (kt & 1) * FSTGB;

        // ---- phase 1: S = Q K^T for both ti; K fragment shared ----
        float s[2][8][4];
        #pragma unroll
        for (int t = 0; t < 2; t++)
            #pragma unroll
            for (int j = 0; j < 8; j++)
                #pragma unroll
                for (int r = 0; r < 4; r++) s[t][j][r] = 0.f;

        #pragma unroll
        for (int ks = 0; ks < 8; ks++) {
            uint32_t a0[4], a1[4];
            uint32_t qa = QH + a_row0 * FROWB + ks * 32 + a_kb;
            LDSM_X4(a0[0], a0[1], a0[2], a0[3], qa);
            LDSM_X4(a1[0], a1[1], a1[2], a1[3], qa + 16 * FROWB);
            #pragma unroll
            for (int bj = 0; bj < 4; bj++) {
                uint32_t ka = kb + (bj * 16 + b_row) * FROWB + ks * 32 + b_kb;
                uint32_t h0, h1, h2, h3;
                LDSM_X4(h0, h1, h2, h3, ka);
                uint32_t bh0[2] = {h0, h1}, bh1[2] = {h2, h3};
                mma16816h(s[0][2 * bj],     a0, bh0);
                mma16816h(s[0][2 * bj + 1], a0, bh1);
                mma16816h(s[1][2 * bj],     a1, bh0);
                mma16816h(s[1][2 * bj + 1], a1, bh1);
            }
        }

        // ---- causal mask (only last two tiles of this block) ----
        if (kt >= 2 * bi) {
            #pragma unroll
            for (int t = 0; t < 2; t++) {
                int row0 = q0 + wq * 32 + t * 16 + er, row1 = row0 + 8;
                int colb = kt * 64 + ec2;
                #pragma unroll
                for (int j = 0; j < 8; j++) {
                    int c0 = colb + j * 8, c1 = c0 + 1;
                    if (c0 > row0) s[t][j][0] = -1e30f;
                    if (c1 > row0) s[t][j][1] = -1e30f;
                    if (c0 > row1) s[t][j][2] = -1e30f;
                    if (c1 > row1) s[t][j][3] = -1e30f;
                }
            }
        }

        // ---- online softmax per ti; pack P (single fp16) in place ----
        uint32_t ph[2][16];
        #pragma unroll
        for (int t = 0; t < 2; t++) {
            float mx0 = -1e30f, mx1 = -1e30f;
            #pragma unroll
            for (int j = 0; j < 8; j++) {
                mx0 = fmaxf(mx0, fmaxf(s[t][j][0], s[t][j][1]));
                mx1 = fmaxf(mx1, fmaxf(s[t][j][2], s[t][j][3]));
            }
            mx0 = fmaxf(mx0, __shfl_xor_sync(0xffffffffu, mx0, 1));
            mx0 = fmaxf(mx0, __shfl_xor_sync(0xffffffffu, mx0, 2));
            mx1 = fmaxf(mx1, __shfl_xor_sync(0xffffffffu, mx1, 1));
            mx1 = fmaxf(mx1, __shfl_xor_sync(0xffffffffu, mx1, 2));
            float mn0 = fmaxf(m[t][0], mx0), mn1 = fmaxf(m[t][1], mx1);
            float al0 = __expf(m[t][0] - mn0), al1 = __expf(m[t][1] - mn1);
            m[t][0] = mn0; m[t][1] = mn1;
            float sm0 = 0.f, sm1 = 0.f;
            #pragma unroll
            for (int j = 0; j < 8; j++) {
                s[t][j][0] = __expf(s[t][j][0] - mn0); sm0 += s[t][j][0];
                s[t][j][1] = __expf(s[t][j][1] - mn0); sm0 += s[t][j][1];
                s[t][j][2] = __expf(s[t][j][2] - mn1); sm1 += s[t][j][2];
                s[t][j][3] = __expf(s[t][j][3] - mn1); sm1 += s[t][j][3];
            }
            sm0 += __shfl_xor_sync(0xffffffffu, sm0, 1);
            sm0 += __shfl_xor_sync(0xffffffffu, sm0, 2);
            sm1 += __shfl_xor_sync(0xffffffffu, sm1, 1);
            sm1 += __shfl_xor_sync(0xffffffffu, sm1, 2);
            l[t][0] = l[t][0] * al0 + sm0;
            l[t][1] = l[t][1] * al1 + sm1;
            #pragma unroll
            for (int j = 0; j < 16; j++) {
                o[t][j][0] *= al0; o[t][j][1] *= al0;
                o[t][j][2] *= al1; o[t][j][3] *= al1;
            }
            #pragma unroll
            for (int ki = 0; ki < 4; ki++) {
                __half2 p0 = __floats2half2_rn(s[t][2 * ki][0],     s[t][2 * ki][1]);
                __half2 p1 = __floats2half2_rn(s[t][2 * ki][2],     s[t][2 * ki][3]);
                __half2 p2 = __floats2half2_rn(s[t][2 * ki + 1][0], s[t][2 * ki + 1][1]);
                __half2 p3 = __floats2half2_rn(s[t][2 * ki + 1][2], s[t][2 * ki + 1][3]);
                ph[t][ki * 4 + 0] = *reinterpret_cast<uint32_t*>(&p0);
                ph[t][ki * 4 + 1] = *reinterpret_cast<uint32_t*>(&p1);
                ph[t][ki * 4 + 2] = *reinterpret_cast<uint32_t*>(&p2);
                ph[t][ki * 4 + 3] = *reinterpret_cast<uint32_t*>(&p3);
            }
        }

        // ---- phase 2: O += P V; V fragment shared across both ti ----
        const uint32_t vbase = kb + FKBYTES;
        #pragma unroll
        for (int ki = 0; ki < 4; ki++) {
            #pragma unroll
            for (int nj = 0; nj < 8; nj++) {
                uint32_t va = vbase + (ki * 16 + v_row) * FROWB + nj * 32 + v_cb;
                uint32_t h0, h1, h2, h3;
                LDSM_X4T(h0, h1, h2, h3, va);
                uint32_t vh0[2] = {h0, h1}, vh1[2] = {h2, h3};
                mma16816h(o[0][2 * nj],     &ph[0][ki * 4], vh0);
                mma16816h(o[0][2 * nj + 1], &ph[0][ki * 4], vh1);
                mma16816h(o[1][2 * nj],     &ph[1][ki * 4], vh0);
                mma16816h(o[1][2 * nj + 1], &ph[1][ki * 4], vh1);
            }
        }
        __syncthreads();   // protect KV buffer before next produce overwrites
    }

    // ---- epilogue: normalize + single fp16 write ----
    #pragma unroll
    for (int t = 0; t < 2; t++) {
        float il0 = 1.f / l[t][0], il1 = 1.f / l[t][1];
        int row0 = q0 + wq * 32 + t * 16 + er;
        #pragma unroll
        for (int j = 0; j < 16; j++) {
            int col = hh * 128 + j * 8 + ec2;
            size_t off0 = ((size_t)b * S_ + row0) * D_ + col;
            size_t off1 = ((size_t)b * S_ + row0 + 8) * D_ + col;
            *(__half2*)(oh_ + off0) = __floats2half2_rn(o[t][j][0] * il0, o[t][j][1] * il0);
            *(__half2*)(oh_ + off1) = __floats2half2_rn(o[t][j][2] * il1, o[t][j][3] * il1);
        }
    }
}

// ---------------------------------------------------------------------------
// Launch
// ---------------------------------------------------------------------------
extern "C" void kernel_launch(void* const* d_in, const int* in_sizes, int n_in,
                              void* d_out, int out_size)
{
    (void)in_sizes; (void)n_in; (void)out_size;
    const float* x    = (const float*)d_in[0];
    const float* Wqkv = (const float*)d_in[1];
    const float* bqkv = (const float*)d_in[2];
    const float* Wo   = (const float*)d_in[3];
    const float* bo   = (const float*)d_in[4];
    float* out = (float*)d_out;

    __half *xh, *w1h, *w2h, *qh, *kh, *vh, *ah;
    cudaGetSymbolAddress((void**)&xh, g_xh);
    cudaGetSymbolAddress((void**)&w1h, g_w1h);   cudaGetSymbolAddress((void**)&w2h, g_w2h);
    cudaGetSymbolAddress((void**)&qh, g_qh);
    cudaGetSymbolAddress((void**)&kh, g_kh);     cudaGetSymbolAddress((void**)&vh, g_vh);
    cudaGetSymbolAddress((void**)&ah, g_ah);

    cudaFuncSetAttribute(gemm_qkv,
                         cudaFuncAttributeMaxDynamicSharedMemorySize, QKV_DYN_SMEM);
    cudaFuncSetAttribute(gemm_proj,
                         cudaFuncAttributeMaxDynamicSharedMemorySize, PROJ_DYN_SMEM);
    cudaFuncSetAttribute(flash_mma,
                         cudaFuncAttributeMaxDynamicSharedMemorySize, FLASH_DYN_SMEM);

    // 1) convert x to single fp16
    {
        int n4 = (M_ * D_) / 4;
        convert_f32_h<<<(n4 + 255) / 256, 256>>>(x, xh, n4);
    }
    // 2) transpose weights to [N,K] fp16
    transpose_h<<<dim3((3 * D_) / 32, D_ / 32), dim3(32, 8)>>>(Wqkv, w1h, D_, 3 * D_);
    transpose_h<<<dim3(D_ / 32, D_ / 32), dim3(32, 8)>>>(Wo, w2h, D_, D_);

    // 3) QKV GEMM (fp16x1, BM=128 BN=96, 2 CTAs/SM, 2048 CTAs)
    gemm_qkv<<<dim3((3 * D_) / 96, M_ / 128), 128, QKV_DYN_SMEM>>>(
        xh, w1h, bqkv, qh, kh, vh);

    // 4) HMMA flash attention (4 warps, BQ=128, 2 CTAs/SM)
    flash_mma<<<dim3(S_ / 128, H_, B_), 128, FLASH_DYN_SMEM>>>(
        qh, kh, vh, ah);

    // 5) out = attn @ Wo + bo  (fp16x1)
    gemm_proj<<<dim3(D_ / 256, M_ / 128), 256, PROJ_DYN_SMEM>>>(
        ah, w2h, bo, out);
}